// round 2
// baseline (speedup 1.0000x reference)
#include <cuda_runtime.h>

#define RES_   0.16f
#define XMIN_ (-51.2f)
#define YMIN_ (-51.2f)
#define EPS_   1e-5f
#define NEG_  (-1000000000.0f)

// Folded-parameter scratch (device globals: allocation-free).
// d_A rows: 0..3 = coeffs for x,y,z,r ; 4..6 = coeffs for xc,yc,z_mean ; 7 = bias t1
__device__ float d_A[8 * 64];
__device__ float d_W2f[64 * 64];
__device__ float d_t2f[64];
__device__ int   d_i64flag;   // 1 -> integer inputs are int64, 0 -> int32

// Detect whether the npts buffer is int64 or int32.
// int64 values are in [0,32], so viewed as int32 pairs every odd (high) word is 0.
// For genuine int32 data, 64 consecutive odd entries all being 0 has prob ~33^-64.
__global__ void pfn_detect(const int* __restrict__ npts_i32) {
    int f = 1;
    #pragma unroll 1
    for (int i = 1; i < 129; i += 2) {
        if (npts_i32[i] != 0) { f = 0; break; }
    }
    d_i64flag = f;
}

__global__ void pfn_prep(const float* __restrict__ W1, const float* __restrict__ b1,
                         const float* __restrict__ g1, const float* __restrict__ beta1,
                         const float* __restrict__ m1, const float* __restrict__ v1,
                         const float* __restrict__ W2, const float* __restrict__ b2,
                         const float* __restrict__ g2, const float* __restrict__ beta2,
                         const float* __restrict__ m2, const float* __restrict__ v2) {
    int c = threadIdx.x;  // 0..63
    float s1 = g1[c] * rsqrtf(v1[c] + EPS_);
    float w0 = W1[0 * 64 + c], w1 = W1[1 * 64 + c], w2 = W1[2 * 64 + c];
    float w3 = W1[3 * 64 + c], w4 = W1[4 * 64 + c], w5 = W1[5 * 64 + c];
    float w6 = W1[6 * 64 + c], w7 = W1[7 * 64 + c], w8 = W1[8 * 64 + c];
    d_A[0 * 64 + c] = (w0 + w4 + w7) * s1;   // x
    d_A[1 * 64 + c] = (w1 + w5 + w8) * s1;   // y
    d_A[2 * 64 + c] = (w2 + w6) * s1;        // z
    d_A[3 * 64 + c] = w3 * s1;               // r
    d_A[4 * 64 + c] = (w4 + w7) * s1;        // xc coeff
    d_A[5 * 64 + c] = (w5 + w8) * s1;        // yc coeff
    d_A[6 * 64 + c] = w6 * s1;               // z_mean coeff
    d_A[7 * 64 + c] = (b1[c] - m1[c]) * s1 + beta1[c];

    float s2 = g2[c] * rsqrtf(v2[c] + EPS_);
    for (int k = 0; k < 64; k++) d_W2f[k * 64 + c] = W2[k * 64 + c] * s2;
    d_t2f[c] = (b2[c] - m2[c]) * s2 + beta2[c];
}

// One warp per pillar. Lane owns channels (lane, lane+32); W2 columns in registers.
__global__ __launch_bounds__(128) void pfn_main(
    const float4* __restrict__ pillars,   // [P*32] float4 (x,y,z,r)
    const void*  __restrict__ coords_raw, // [P*2] int32 or int64 (row, col)
    const void*  __restrict__ npts_raw,   // [P]   int32 or int64
    float* __restrict__ out, int P)
{
    const int warp = threadIdx.x >> 5;
    const int lane = threadIdx.x & 31;
    const int p = blockIdx.x * 4 + warp;

    __shared__ float4 h1buf4[4][16];  // per-warp 64-float h1, 16B-aligned

    if (p >= P) return;

    const int i64 = d_i64flag;

    // --- dtype-robust integer loads (uniform branch) ---
    int npts;
    float crow, ccol;
    if (i64) {
        npts = (int)((const long long*)npts_raw)[p];
        crow = (float)((const long long*)coords_raw)[p * 2 + 0];
        ccol = (float)((const long long*)coords_raw)[p * 2 + 1];
    } else {
        npts = ((const int*)npts_raw)[p];
        crow = (float)((const int*)coords_raw)[p * 2 + 0];
        ccol = (float)((const int*)coords_raw)[p * 2 + 1];
    }
    npts = min(max(npts, 0), 32);   // structural hang guard + matches semantics

    // Each lane holds one point of this pillar in registers.
    const float4 pt = pillars[p * 32 + lane];

    // Masked z mean (warp butterfly reduce).
    float zs = (lane < npts) ? pt.z : 0.0f;
    #pragma unroll
    for (int o = 16; o; o >>= 1) zs += __shfl_xor_sync(0xFFFFFFFFu, zs, o);
    const float zm = zs / fmaxf((float)npts, 1.0f);

    const float xc = (ccol + 0.5f) * RES_ + XMIN_;
    const float yc = (crow + 0.5f) * RES_ + YMIN_;

    const int c0 = lane, c1 = lane + 32;

    // Layer-1 folded coefficients for the two channels this lane owns.
    const float ax0 = d_A[0 * 64 + c0], ay0 = d_A[1 * 64 + c0];
    const float az0 = d_A[2 * 64 + c0], ar0 = d_A[3 * 64 + c0];
    const float ax1 = d_A[0 * 64 + c1], ay1 = d_A[1 * 64 + c1];
    const float az1 = d_A[2 * 64 + c1], ar1 = d_A[3 * 64 + c1];
    const float bias0 = d_A[7 * 64 + c0] - xc * d_A[4 * 64 + c0]
                      - yc * d_A[5 * 64 + c0] - zm * d_A[6 * 64 + c0];
    const float bias1 = d_A[7 * 64 + c1] - xc * d_A[4 * 64 + c1]
                      - yc * d_A[5 * 64 + c1] - zm * d_A[6 * 64 + c1];

    // W2 columns in registers (coalesced loads across lanes, L1-resident).
    float w2a[64], w2b[64];
    #pragma unroll
    for (int k = 0; k < 64; k++) {
        w2a[k] = d_W2f[k * 64 + c0];
        w2b[k] = d_W2f[k * 64 + c1];
    }
    const float t20 = d_t2f[c0], t21 = d_t2f[c1];

    float acc0 = NEG_, acc1 = NEG_;
    float* h1s = (float*)h1buf4[warp];

    for (int j = 0; j < npts; j++) {
        // Broadcast point j from lane j.
        const float x  = __shfl_sync(0xFFFFFFFFu, pt.x, j);
        const float y  = __shfl_sync(0xFFFFFFFFu, pt.y, j);
        const float zz = __shfl_sync(0xFFFFFFFFu, pt.z, j);
        const float r  = __shfl_sync(0xFFFFFFFFu, pt.w, j);

        // Layer 1 (folded BN + rank-4 feature collapse) + ReLU.
        float h0 = fmaf(ax0, x, fmaf(ay0, y, fmaf(az0, zz, fmaf(ar0, r, bias0))));
        float h1 = fmaf(ax1, x, fmaf(ay1, y, fmaf(az1, zz, fmaf(ar1, r, bias1))));
        h0 = fmaxf(h0, 0.0f);
        h1 = fmaxf(h1, 0.0f);

        __syncwarp();           // previous iteration's reads done
        h1s[c0] = h0;
        h1s[c1] = h1;
        __syncwarp();           // stores visible

        // Layer 2: two 64-dot products, weights in regs, h1 via LDS.128 broadcast.
        float o0a = 0.f, o0b = 0.f, o1a = 0.f, o1b = 0.f;
        #pragma unroll
        for (int k = 0; k < 16; k++) {
            const float4 h4 = h1buf4[warp][k];
            o0a = fmaf(h4.x, w2a[4 * k + 0], o0a);
            o0b = fmaf(h4.y, w2a[4 * k + 1], o0b);
            o0a = fmaf(h4.z, w2a[4 * k + 2], o0a);
            o0b = fmaf(h4.w, w2a[4 * k + 3], o0b);
            o1a = fmaf(h4.x, w2b[4 * k + 0], o1a);
            o1b = fmaf(h4.y, w2b[4 * k + 1], o1b);
            o1a = fmaf(h4.z, w2b[4 * k + 2], o1a);
            o1b = fmaf(h4.w, w2b[4 * k + 3], o1b);
        }
        const float o0 = fmaxf(t20 + (o0a + o0b), 0.0f);
        const float o1 = fmaxf(t21 + (o1a + o1b), 0.0f);
        acc0 = fmaxf(acc0, o0);
        acc1 = fmaxf(acc1, o1);
    }

    out[p * 64 + c0] = acc0;
    out[p * 64 + c1] = acc1;
}

extern "C" void kernel_launch(void* const* d_in, const int* in_sizes, int n_in,
                              void* d_out, int out_size) {
    const float* pillars = (const float*)d_in[0];   // (P,32,4) f32
    const void*  coords  = d_in[1];                 // (P,2) int32 or int64
    const void*  npts    = d_in[2];                 // (P,)  int32 or int64
    const float* W1    = (const float*)d_in[3];
    const float* b1    = (const float*)d_in[4];
    const float* g1    = (const float*)d_in[5];
    const float* beta1 = (const float*)d_in[6];
    const float* m1    = (const float*)d_in[7];
    const float* v1    = (const float*)d_in[8];
    const float* W2    = (const float*)d_in[9];
    const float* b2    = (const float*)d_in[10];
    const float* g2    = (const float*)d_in[11];
    const float* beta2 = (const float*)d_in[12];
    const float* m2    = (const float*)d_in[13];
    const float* v2    = (const float*)d_in[14];

    const int P = in_sizes[2];  // element count of num_points_per_pillar

    pfn_detect<<<1, 1>>>((const int*)npts);
    pfn_prep<<<1, 64>>>(W1, b1, g1, beta1, m1, v1, W2, b2, g2, beta2, m2, v2);

    const int warpsPerBlock = 4;
    const int blocks = (P + warpsPerBlock - 1) / warpsPerBlock;
    pfn_main<<<blocks, warpsPerBlock * 32>>>(
        (const float4*)pillars, coords, npts, (float*)d_out, P);
}